// round 2
// baseline (speedup 1.0000x reference)
#include <cuda_runtime.h>
#include <cuda_bf16.h>

#define N_NODES 100000
#define N_EDGES 1000000
#define N_GRAPHS 512
#define HDIM 64

// ---------------- scratch (device globals: allocation-free) ----------------
__device__ __align__(16) float g_dinv[N_NODES];
__device__ __align__(16) float g_norm[N_EDGES];
__device__ __align__(16) float g_xw [N_NODES * HDIM];
__device__ __align__(16) float g_agg[N_NODES * HDIM];
__device__ __align__(16) float g_gmax[N_GRAPHS * HDIM];
__device__ __align__(16) float g_gsum[N_GRAPHS * HDIM];
__device__ float g_gcnt[N_GRAPHS];

// ---------------- norm precompute ----------------
__global__ void k_deg_init() {
    int i = blockIdx.x * blockDim.x + threadIdx.x;
    if (i < N_NODES) g_dinv[i] = 1.0f;  // self-loop
}

__global__ void k_deg_count(const int* __restrict__ col) {
    int e = blockIdx.x * blockDim.x + threadIdx.x;
    if (e < N_EDGES) atomicAdd(&g_dinv[col[e]], 1.0f);
}

__global__ void k_dinv() {
    int i = blockIdx.x * blockDim.x + threadIdx.x;
    if (i < N_NODES) g_dinv[i] = rsqrtf(g_dinv[i]);  // deg >= 1 always
}

__global__ void k_norm(const int* __restrict__ row, const int* __restrict__ col) {
    int e = blockIdx.x * blockDim.x + threadIdx.x;
    if (e < N_EDGES) g_norm[e] = g_dinv[row[e]] * g_dinv[col[e]];
}

// ---------------- fused GEMM: xw = act(src) @ W ; agg = dinv^2 * xw -------
// src == nullptr means "read from g_agg" (resolved in DEVICE code; never pass
// a __device__ symbol from host).
// act(v) = FUSE ? relu(v + bias_prev[k]) : v
// Block: 256 threads handles 16 rows. Each thread: 1 row, 4 cols (jg+16m).
template <int K, bool FUSE>
__global__ void k_gemm(const float* src, const float* __restrict__ W,
                       const float* __restrict__ bias_prev) {
    constexpr int WS = K + 4;  // padded stride
    __shared__ __align__(16) float Wt[64 * WS];  // Wt[j][k] = W[k][j]
    __shared__ __align__(16) float S[16 * K];    // staged (activated) src rows

    const float* s = src ? src : g_agg;  // device-side resolution
    const int tid  = threadIdx.x;
    const int base = blockIdx.x * 16;

    // load + transpose W (coalesced over j)
    for (int t = tid; t < 64 * K; t += 256) {
        int j = t & 63, k = t >> 6;
        Wt[j * WS + k] = W[k * 64 + j];
    }
    // stage src rows (apply prev bias + relu if fused)
    for (int t = tid; t < 16 * K; t += 256) {
        int r = t / K, k = t - r * K;
        float v = s[(long)(base + r) * K + k];
        if (FUSE) v = fmaxf(v + bias_prev[k], 0.0f);
        S[r * K + k] = v;
    }
    __syncthreads();

    const int r  = tid >> 4;
    const int jg = tid & 15;
    float acc[4] = {0.f, 0.f, 0.f, 0.f};

#pragma unroll
    for (int k4 = 0; k4 < K / 4; k4++) {
        float4 a = *(const float4*)&S[r * K + k4 * 4];
#pragma unroll
        for (int m = 0; m < 4; m++) {
            float4 w = *(const float4*)&Wt[(jg + 16 * m) * WS + k4 * 4];
            acc[m] += a.x * w.x + a.y * w.y + a.z * w.z + a.w * w.w;
        }
    }
    __syncthreads();  // all reads of s (== g_agg) done before overwriting below

    const int  node = base + r;
    const float dv  = g_dinv[node];
    const float d2  = dv * dv;
#pragma unroll
    for (int m = 0; m < 4; m++) {
        int j = jg + 16 * m;
        float v = acc[m];
        g_xw [(long)node * 64 + j] = v;
        g_agg[(long)node * 64 + j] = d2 * v;  // self-loop init
    }
}

// ---------------- edge scatter: agg[col] += norm * xw[row] ---------------
// 16 threads per edge, one float4 each, vector red.
__global__ void k_scatter(const int* __restrict__ rows, const int* __restrict__ cols) {
    long gid = (long)blockIdx.x * blockDim.x + threadIdx.x;
    int e = (int)(gid >> 4);
    if (e >= N_EDGES) return;
    int t = (int)(gid & 15);
    int r = rows[e], c = cols[e];
    float nm = g_norm[e];
    float4 v = *((const float4*)g_xw + (long)r * 16 + t);
    float* p = g_agg + (long)c * 64 + t * 4;
    asm volatile("red.global.add.v4.f32 [%0], {%1,%2,%3,%4};"
                 :: "l"(p), "f"(v.x * nm), "f"(v.y * nm), "f"(v.z * nm), "f"(v.w * nm)
                 : "memory");
}

// ---------------- pooling ----------------
__global__ void k_pool_zero() {
    int i = blockIdx.x * blockDim.x + threadIdx.x;
    if (i < N_GRAPHS * HDIM) { g_gmax[i] = 0.0f; g_gsum[i] = 0.0f; }
    if (i < N_GRAPHS) g_gcnt[i] = 0.0f;
}

// h = relu(agg + b4); segment max/sum/count over sorted batch_index.
// Block 256: j = tid&63, y = tid>>6; each (y) handles 128 contiguous nodes.
__global__ void k_pool(const float* __restrict__ b4, const int* __restrict__ batch) {
    int j = threadIdx.x & 63;
    int y = threadIdx.x >> 6;
    int start = blockIdx.x * 512 + y * 128;
    int end   = min(start + 128, N_NODES);
    if (start >= end) return;

    float bj = b4[j];
    int   curg = batch[start];
    float mx = 0.f, sm = 0.f;
    int   cnt = 0;

    for (int n = start; n < end; n++) {
        int g = batch[n];
        if (g != curg) {
            atomicMax((int*)&g_gmax[curg * 64 + j], __float_as_int(mx));
            atomicAdd(&g_gsum[curg * 64 + j], sm);
            if (j == 0) atomicAdd(&g_gcnt[curg], (float)cnt);
            curg = g; mx = 0.f; sm = 0.f; cnt = 0;
        }
        float v = fmaxf(g_agg[(long)n * 64 + j] + bj, 0.0f);
        mx = fmaxf(mx, v);
        sm += v;
        cnt++;
    }
    atomicMax((int*)&g_gmax[curg * 64 + j], __float_as_int(mx));
    atomicAdd(&g_gsum[curg * 64 + j], sm);
    if (j == 0) atomicAdd(&g_gcnt[curg], (float)cnt);
}

// ---------------- head: hg = [gmax | gmean], out = hg @ Wo + bo ----------
__global__ void k_head(const float* __restrict__ Wo, const float* __restrict__ bo,
                       float* __restrict__ out, int write_hg) {
    int g = blockIdx.x;
    int j = threadIdx.x;  // 0..127
    float cnt = fmaxf(g_gcnt[g], 1.0f);
    float val = (j < 64) ? g_gmax[g * 64 + j] : g_gsum[g * 64 + (j - 64)] / cnt;
    if (write_hg) out[N_GRAPHS + (long)g * 128 + j] = val;

    float p = val * Wo[j];
#pragma unroll
    for (int off = 16; off > 0; off >>= 1)
        p += __shfl_down_sync(0xffffffff, p, off);

    __shared__ float red[4];
    if ((j & 31) == 0) red[j >> 5] = p;
    __syncthreads();
    if (j == 0) out[g] = red[0] + red[1] + red[2] + red[3] + bo[0];
}

// ---------------- launch ----------------
extern "C" void kernel_launch(void* const* d_in, const int* in_sizes, int n_in,
                              void* d_out, int out_size) {
    const float* x     = (const float*)d_in[0];
    const int*   ei    = (const int*)  d_in[1];   // [2, E] flattened
    const int*   batch = (const int*)  d_in[2];
    const float* W1 = (const float*)d_in[3];  const float* b1 = (const float*)d_in[4];
    const float* W2 = (const float*)d_in[5];  const float* b2 = (const float*)d_in[6];
    const float* W3 = (const float*)d_in[7];  const float* b3 = (const float*)d_in[8];
    const float* W4 = (const float*)d_in[9];  const float* b4 = (const float*)d_in[10];
    const float* Wo = (const float*)d_in[11]; const float* bo = (const float*)d_in[12];

    const int* rows = ei;            // source
    const int* cols = ei + N_EDGES;  // target (aggregation)

    float* out = (float*)d_out;
    int write_hg = (out_size >= N_GRAPHS + N_GRAPHS * 2 * HDIM) ? 1 : 0;

    const int NB_N = (N_NODES + 255) / 256;
    const int NB_E = (N_EDGES + 255) / 256;

    // norm precompute
    k_deg_init <<<NB_N, 256>>>();
    k_deg_count<<<NB_E, 256>>>(cols);
    k_dinv     <<<NB_N, 256>>>();
    k_norm     <<<NB_E, 256>>>(rows, cols);

    const int GEMM_BLKS = N_NODES / 16;        // 6250 (exact)
    const int SCAT_BLKS = N_EDGES * 16 / 256;  // 62500 (exact)

    // layer 1 (input x, K=8, no fused activation)
    k_gemm<8, false><<<GEMM_BLKS, 256>>>(x, W1, nullptr);
    k_scatter<<<SCAT_BLKS, 256>>>(rows, cols);
    // layers 2..4 (src = nullptr -> g_agg of previous layer, fused bias+relu)
    k_gemm<64, true><<<GEMM_BLKS, 256>>>(nullptr, W2, b1);
    k_scatter<<<SCAT_BLKS, 256>>>(rows, cols);
    k_gemm<64, true><<<GEMM_BLKS, 256>>>(nullptr, W3, b2);
    k_scatter<<<SCAT_BLKS, 256>>>(rows, cols);
    k_gemm<64, true><<<GEMM_BLKS, 256>>>(nullptr, W4, b3);
    k_scatter<<<SCAT_BLKS, 256>>>(rows, cols);

    // pooling + head
    k_pool_zero<<<(N_GRAPHS * HDIM + 255) / 256, 256>>>();
    k_pool<<<(N_NODES + 511) / 512, 256>>>(b4, batch);
    k_head<<<N_GRAPHS, 128>>>(Wo, bo, out, write_hg);
}

// round 3
// speedup vs baseline: 1.2435x; 1.2435x over previous
#include <cuda_runtime.h>
#include <cuda_bf16.h>

#define N_NODES 100000
#define N_EDGES 1000000
#define N_GRAPHS 512
#define HDIM 64
#define SCAN_B 1024
#define SCAN_NB ((N_NODES + SCAN_B - 1) / SCAN_B)   // 98

// ---------------- scratch (device globals; never passed from host) --------
__device__ __align__(16) float  g_dinv[N_NODES];
__device__ __align__(16) int    g_deg [N_NODES];
__device__ __align__(16) int    g_off [N_NODES + 1];
__device__ __align__(16) int    g_cur [N_NODES];
__device__ __align__(16) int    g_bsum[SCAN_NB];
__device__ __align__(16) int    g_bpre[SCAN_NB];
__device__ __align__(16) float2 g_csr [N_EDGES];          // (src_as_int, norm)
__device__ __align__(16) float  g_xw  [N_NODES * HDIM];
__device__ __align__(16) float  g_agg [N_NODES * HDIM];
__device__ __align__(16) float  g_aggx[N_NODES * 8];
__device__ __align__(16) float  g_gmax[N_GRAPHS * HDIM];
__device__ __align__(16) float  g_gsum[N_GRAPHS * HDIM];
__device__ float g_gcnt[N_GRAPHS];

// ---------------- init: zero deg + pooling buffers ------------------------
__global__ void k_zero() {
    int i = blockIdx.x * blockDim.x + threadIdx.x;
    if (i < N_NODES) g_deg[i] = 0;
    if (i < N_GRAPHS * HDIM) { g_gmax[i] = 0.0f; g_gsum[i] = 0.0f; }
    if (i < N_GRAPHS) g_gcnt[i] = 0.0f;
}

__global__ void k_deg_count(const int* __restrict__ col) {
    int e = blockIdx.x * blockDim.x + threadIdx.x;
    if (e < N_EDGES) atomicAdd(&g_deg[col[e]], 1);
}

__global__ void k_dinv() {
    int i = blockIdx.x * blockDim.x + threadIdx.x;
    if (i < N_NODES) g_dinv[i] = rsqrtf((float)(g_deg[i] + 1));  // +1 self-loop
}

// ---------------- exclusive scan of g_deg -> g_off ------------------------
__global__ void k_scan1() {   // grid SCAN_NB, block 1024
    __shared__ int sh[SCAN_B];
    int idx = threadIdx.x;
    int n = blockIdx.x * SCAN_B + idx;
    int v = (n < N_NODES) ? g_deg[n] : 0;
    sh[idx] = v;
    __syncthreads();
#pragma unroll
    for (int d = 1; d < SCAN_B; d <<= 1) {
        int t = (idx >= d) ? sh[idx - d] : 0;
        __syncthreads();
        sh[idx] += t;
        __syncthreads();
    }
    if (n < N_NODES) g_off[n] = sh[idx] - v;          // exclusive (local)
    if (idx == SCAN_B - 1) g_bsum[blockIdx.x] = sh[idx];
}

__global__ void k_scan2() {   // 1 thread: 98 adds
    if (threadIdx.x == 0) {
        int acc = 0;
        for (int b = 0; b < SCAN_NB; b++) { g_bpre[b] = acc; acc += g_bsum[b]; }
    }
}

__global__ void k_scan3() {
    int n = blockIdx.x * blockDim.x + threadIdx.x;
    if (n < N_NODES) {
        int o = g_off[n] + g_bpre[n >> 10];
        g_off[n] = o;
        g_cur[n] = o;
    }
    if (n == 0) g_off[N_NODES] = N_EDGES;
}

// ---------------- CSR fill: packed (src, dinv[r]*dinv[c]) -----------------
__global__ void k_fill(const int* __restrict__ rows, const int* __restrict__ cols) {
    int e = blockIdx.x * blockDim.x + threadIdx.x;
    if (e >= N_EDGES) return;
    int r = rows[e], c = cols[e];
    int slot = atomicAdd(&g_cur[c], 1);
    g_csr[slot] = make_float2(__int_as_float(r), g_dinv[r] * g_dinv[c]);
}

// ---------------- gather_x: g_aggx = A_hat @ x (8-dim) --------------------
// 2 threads per node, one float4 slice each.
__global__ void k_gather_x(const float* __restrict__ x) {
    int gid = blockIdx.x * blockDim.x + threadIdx.x;
    int n = gid >> 1, t = gid & 1;
    if (n >= N_NODES) return;
    const float4* x4 = (const float4*)x;
    int o0 = g_off[n], o1 = g_off[n + 1];
    float dv = g_dinv[n];
    float4 acc = x4[(long)n * 2 + t];
    float d2 = dv * dv;
    acc.x *= d2; acc.y *= d2; acc.z *= d2; acc.w *= d2;
    int i = o0;
    for (; i + 2 <= o1; i += 2) {
        float2 e0 = g_csr[i], e1 = g_csr[i + 1];
        float4 v0 = x4[(long)__float_as_int(e0.x) * 2 + t];
        float4 v1 = x4[(long)__float_as_int(e1.x) * 2 + t];
        acc.x = fmaf(e0.y, v0.x, acc.x); acc.y = fmaf(e0.y, v0.y, acc.y);
        acc.z = fmaf(e0.y, v0.z, acc.z); acc.w = fmaf(e0.y, v0.w, acc.w);
        acc.x = fmaf(e1.y, v1.x, acc.x); acc.y = fmaf(e1.y, v1.y, acc.y);
        acc.z = fmaf(e1.y, v1.z, acc.z); acc.w = fmaf(e1.y, v1.w, acc.w);
    }
    if (i < o1) {
        float2 e0 = g_csr[i];
        float4 v0 = x4[(long)__float_as_int(e0.x) * 2 + t];
        acc.x = fmaf(e0.y, v0.x, acc.x); acc.y = fmaf(e0.y, v0.y, acc.y);
        acc.z = fmaf(e0.y, v0.z, acc.z); acc.w = fmaf(e0.y, v0.w, acc.w);
    }
    ((float4*)g_aggx)[(long)n * 2 + t] = acc;
}

// ---------------- gather64: g_agg = A_hat @ g_xw --------------------------
// 16 threads per node, one float4 slice each; CSR entries broadcast.
__global__ void k_gather64() {
    int gid = blockIdx.x * blockDim.x + threadIdx.x;   // exact grid: N*16
    int n = gid >> 4, t = gid & 15;
    const float4* xw4 = (const float4*)g_xw;
    int o0 = g_off[n], o1 = g_off[n + 1];
    float dv = g_dinv[n];
    float4 acc = xw4[(long)n * 16 + t];
    float d2 = dv * dv;
    acc.x *= d2; acc.y *= d2; acc.z *= d2; acc.w *= d2;
    int i = o0;
    for (; i + 2 <= o1; i += 2) {
        float2 e0 = g_csr[i], e1 = g_csr[i + 1];
        float4 v0 = xw4[(long)__float_as_int(e0.x) * 16 + t];
        float4 v1 = xw4[(long)__float_as_int(e1.x) * 16 + t];
        acc.x = fmaf(e0.y, v0.x, acc.x); acc.y = fmaf(e0.y, v0.y, acc.y);
        acc.z = fmaf(e0.y, v0.z, acc.z); acc.w = fmaf(e0.y, v0.w, acc.w);
        acc.x = fmaf(e1.y, v1.x, acc.x); acc.y = fmaf(e1.y, v1.y, acc.y);
        acc.z = fmaf(e1.y, v1.z, acc.z); acc.w = fmaf(e1.y, v1.w, acc.w);
    }
    if (i < o1) {
        float2 e0 = g_csr[i];
        float4 v0 = xw4[(long)__float_as_int(e0.x) * 16 + t];
        acc.x = fmaf(e0.y, v0.x, acc.x); acc.y = fmaf(e0.y, v0.y, acc.y);
        acc.z = fmaf(e0.y, v0.z, acc.z); acc.w = fmaf(e0.y, v0.w, acc.w);
    }
    ((float4*)g_agg)[(long)n * 16 + t] = acc;
}

// ---------------- GEMM: g_xw = act(src) @ W -------------------------------
// SRC: 0 = param pointer, 1 = g_xw (in-place, block-local), 2 = g_agg, 3 = g_aggx
// act(v) = FUSE ? relu(v + bias_prev[k]) : v
template <int K, bool FUSE, int SRC>
__global__ void k_gemm(const float* srcp, const float* __restrict__ W,
                       const float* __restrict__ bias_prev) {
    constexpr int WS = K + 4;
    __shared__ __align__(16) float Wt[64 * WS];  // Wt[j][k] = W[k][j]
    __shared__ __align__(16) float S[16 * K];

    const float* s = (SRC == 0) ? srcp : (SRC == 1) ? g_xw : (SRC == 2) ? g_agg : g_aggx;
    const int tid  = threadIdx.x;
    const int base = blockIdx.x * 16;

    for (int t = tid; t < 64 * K; t += 256) {
        int j = t & 63, k = t >> 6;
        Wt[j * WS + k] = W[k * 64 + j];
    }
    for (int t = tid; t < 16 * K; t += 256) {
        int r = t / K, k = t - r * K;
        float v = s[(long)(base + r) * K + k];
        if (FUSE) v = fmaxf(v + bias_prev[k], 0.0f);
        S[r * K + k] = v;
    }
    __syncthreads();

    const int r  = tid >> 4;
    const int jg = tid & 15;
    float acc[4] = {0.f, 0.f, 0.f, 0.f};
#pragma unroll
    for (int k4 = 0; k4 < K / 4; k4++) {
        float4 a = *(const float4*)&S[r * K + k4 * 4];
#pragma unroll
        for (int m = 0; m < 4; m++) {
            float4 w = *(const float4*)&Wt[(jg + 16 * m) * WS + k4 * 4];
            acc[m] += a.x * w.x + a.y * w.y + a.z * w.z + a.w * w.w;
        }
    }

    const int node = base + r;
#pragma unroll
    for (int m = 0; m < 4; m++)
        g_xw[(long)node * 64 + jg + 16 * m] = acc[m];
}

// ---------------- pooling (sorted batch, run-length flush) ----------------
__global__ void k_pool(const float* __restrict__ b4, const int* __restrict__ batch) {
    int j = threadIdx.x & 63;
    int y = threadIdx.x >> 6;
    int start = blockIdx.x * 512 + y * 128;
    int end   = min(start + 128, N_NODES);
    if (start >= end) return;

    float bj = b4[j];
    int   curg = batch[start];
    float mx = 0.f, sm = 0.f;
    int   cnt = 0;

    for (int n = start; n < end; n++) {
        int g = batch[n];
        if (g != curg) {
            atomicMax((int*)&g_gmax[curg * 64 + j], __float_as_int(mx));
            atomicAdd(&g_gsum[curg * 64 + j], sm);
            if (j == 0) atomicAdd(&g_gcnt[curg], (float)cnt);
            curg = g; mx = 0.f; sm = 0.f; cnt = 0;
        }
        float v = fmaxf(g_agg[(long)n * 64 + j] + bj, 0.0f);
        mx = fmaxf(mx, v);
        sm += v;
        cnt++;
    }
    atomicMax((int*)&g_gmax[curg * 64 + j], __float_as_int(mx));
    atomicAdd(&g_gsum[curg * 64 + j], sm);
    if (j == 0) atomicAdd(&g_gcnt[curg], (float)cnt);
}

// ---------------- head ----------------------------------------------------
__global__ void k_head(const float* __restrict__ Wo, const float* __restrict__ bo,
                       float* __restrict__ out, int write_hg) {
    int g = blockIdx.x;
    int j = threadIdx.x;  // 0..127
    float cnt = fmaxf(g_gcnt[g], 1.0f);
    float val = (j < 64) ? g_gmax[g * 64 + j] : g_gsum[g * 64 + (j - 64)] / cnt;
    if (write_hg) out[N_GRAPHS + (long)g * 128 + j] = val;

    float p = val * Wo[j];
#pragma unroll
    for (int off = 16; off > 0; off >>= 1)
        p += __shfl_down_sync(0xffffffff, p, off);

    __shared__ float red[4];
    if ((j & 31) == 0) red[j >> 5] = p;
    __syncthreads();
    if (j == 0) out[g] = red[0] + red[1] + red[2] + red[3] + bo[0];
}

// ---------------- launch ---------------------------------------------------
extern "C" void kernel_launch(void* const* d_in, const int* in_sizes, int n_in,
                              void* d_out, int out_size) {
    const float* x     = (const float*)d_in[0];
    const int*   ei    = (const int*)  d_in[1];   // [2, E]
    const int*   batch = (const int*)  d_in[2];
    const float* W1 = (const float*)d_in[3];  const float* b1 = (const float*)d_in[4];
    const float* W2 = (const float*)d_in[5];  const float* b2 = (const float*)d_in[6];
    const float* W3 = (const float*)d_in[7];  const float* b3 = (const float*)d_in[8];
    const float* W4 = (const float*)d_in[9];  const float* b4 = (const float*)d_in[10];
    const float* Wo = (const float*)d_in[11]; const float* bo = (const float*)d_in[12];

    const int* rows = ei;            // source
    const int* cols = ei + N_EDGES;  // target

    float* out = (float*)d_out;
    int write_hg = (out_size >= N_GRAPHS + N_GRAPHS * 2 * HDIM) ? 1 : 0;

    const int NB_N = (N_NODES + 255) / 256;
    const int NB_E = (N_EDGES + 255) / 256;

    // CSR build
    k_zero     <<<NB_N, 256>>>();
    k_deg_count<<<NB_E, 256>>>(cols);
    k_dinv     <<<NB_N, 256>>>();
    k_scan1    <<<SCAN_NB, SCAN_B>>>();
    k_scan2    <<<1, 32>>>();
    k_scan3    <<<NB_N, 256>>>();
    k_fill     <<<NB_E, 256>>>(rows, cols);

    const int GEMM_BLKS = N_NODES / 16;          // 6250
    const int G64_BLKS  = N_NODES * 16 / 256;    // 6250 (exact)
    const int GX_BLKS   = (N_NODES * 2 + 255) / 256;

    // layer 1: aggregate 8-dim input first, then GEMM
    k_gather_x<<<GX_BLKS, 256>>>(x);
    k_gemm<8, false, 3><<<GEMM_BLKS, 256>>>(nullptr, W1, nullptr);   // g_xw = preact1
    // layer 2: xw2 = relu(preact1+b1) @ W2 (in-place), then aggregate
    k_gemm<64, true, 1><<<GEMM_BLKS, 256>>>(nullptr, W2, b1);
    k_gather64<<<G64_BLKS, 256>>>();                                  // g_agg = preact2
    // layer 3
    k_gemm<64, true, 2><<<GEMM_BLKS, 256>>>(nullptr, W3, b2);
    k_gather64<<<G64_BLKS, 256>>>();                                  // preact3
    // layer 4
    k_gemm<64, true, 2><<<GEMM_BLKS, 256>>>(nullptr, W4, b3);
    k_gather64<<<G64_BLKS, 256>>>();                                  // preact4

    // pooling + head (relu(+b4) fused in pool)
    k_pool<<<(N_NODES + 511) / 512, 256>>>(b4, batch);
    k_head<<<N_GRAPHS, 128>>>(Wo, bo, out, write_hg);
}

// round 4
// speedup vs baseline: 1.6504x; 1.3271x over previous
#include <cuda_runtime.h>
#include <cuda_bf16.h>

#define N_NODES 100000
#define N_EDGES 1000000
#define N_GRAPHS 512
#define HDIM 64
#define SCAN_B 1024
#define SCAN_NB ((N_NODES + SCAN_B - 1) / SCAN_B)   // 98

// ---------------- scratch (device globals; never passed from host) --------
__device__ __align__(16) float  g_dinv[N_NODES];
__device__ __align__(16) int    g_deg [N_NODES];
__device__ __align__(16) int    g_off [N_NODES + 1];
__device__ __align__(16) int    g_cur [N_NODES];
__device__ __align__(16) int    g_bsum[SCAN_NB];
__device__ __align__(16) int    g_bpre[SCAN_NB];
__device__ __align__(16) float2 g_csr [N_EDGES];          // (src_as_int, norm)
__device__ __align__(16) float  g_xw  [N_NODES * HDIM];
__device__ __align__(16) float  g_agg [N_NODES * HDIM];
__device__ __align__(16) float  g_aggx[N_NODES * 8];
__device__ __align__(16) float  g_gmax[N_GRAPHS * HDIM];
__device__ __align__(16) float  g_gsum[N_GRAPHS * HDIM];
__device__ float g_gcnt[N_GRAPHS];

// ---------------- init: zero deg + pooling buffers ------------------------
__global__ void k_zero() {
    int i = blockIdx.x * blockDim.x + threadIdx.x;
    if (i < N_NODES) g_deg[i] = 0;
    if (i < N_GRAPHS * HDIM) { g_gmax[i] = 0.0f; g_gsum[i] = 0.0f; }
    if (i < N_GRAPHS) g_gcnt[i] = 0.0f;
}

__global__ void k_deg_count(const int* __restrict__ col) {
    int e = blockIdx.x * blockDim.x + threadIdx.x;
    if (e < N_EDGES) atomicAdd(&g_deg[col[e]], 1);
}

// ---------------- exclusive scan of g_deg -> g_off (+ dinv fused) ---------
__global__ void k_scan1() {   // grid SCAN_NB, block 1024
    __shared__ int sh[SCAN_B];
    int idx = threadIdx.x;
    int n = blockIdx.x * SCAN_B + idx;
    int v = (n < N_NODES) ? g_deg[n] : 0;
    if (n < N_NODES) g_dinv[n] = rsqrtf((float)(v + 1));  // +1 self-loop
    sh[idx] = v;
    __syncthreads();
#pragma unroll
    for (int d = 1; d < SCAN_B; d <<= 1) {
        int t = (idx >= d) ? sh[idx - d] : 0;
        __syncthreads();
        sh[idx] += t;
        __syncthreads();
    }
    if (n < N_NODES) g_off[n] = sh[idx] - v;          // exclusive (local)
    if (idx == SCAN_B - 1) g_bsum[blockIdx.x] = sh[idx];
}

__global__ void k_scan2() {   // 1 thread: 98 adds
    if (threadIdx.x == 0) {
        int acc = 0;
        for (int b = 0; b < SCAN_NB; b++) { g_bpre[b] = acc; acc += g_bsum[b]; }
    }
}

__global__ void k_scan3() {
    int n = blockIdx.x * blockDim.x + threadIdx.x;
    if (n < N_NODES) {
        int o = g_off[n] + g_bpre[n >> 10];
        g_off[n] = o;
        g_cur[n] = o;
    }
    if (n == 0) g_off[N_NODES] = N_EDGES;
}

// ---------------- CSR fill: packed (src, dinv[r]*dinv[c]) -----------------
__global__ void k_fill(const int* __restrict__ rows, const int* __restrict__ cols) {
    int e = blockIdx.x * blockDim.x + threadIdx.x;
    if (e >= N_EDGES) return;
    int r = rows[e], c = cols[e];
    int slot = atomicAdd(&g_cur[c], 1);
    g_csr[slot] = make_float2(__int_as_float(r), g_dinv[r] * g_dinv[c]);
}

// ---------------- gather_x: g_aggx = A_hat @ x (8-dim) --------------------
__global__ void k_gather_x(const float* __restrict__ x) {
    int gid = blockIdx.x * blockDim.x + threadIdx.x;
    int n = gid >> 1, t = gid & 1;
    if (n >= N_NODES) return;
    const float4* x4 = (const float4*)x;
    int o0 = g_off[n], o1 = g_off[n + 1];
    float dv = g_dinv[n];
    float4 acc = x4[(long)n * 2 + t];
    float d2 = dv * dv;
    acc.x *= d2; acc.y *= d2; acc.z *= d2; acc.w *= d2;
    int i = o0;
    for (; i + 2 <= o1; i += 2) {
        float2 e0 = g_csr[i], e1 = g_csr[i + 1];
        float4 v0 = x4[(long)__float_as_int(e0.x) * 2 + t];
        float4 v1 = x4[(long)__float_as_int(e1.x) * 2 + t];
        acc.x = fmaf(e0.y, v0.x, acc.x); acc.y = fmaf(e0.y, v0.y, acc.y);
        acc.z = fmaf(e0.y, v0.z, acc.z); acc.w = fmaf(e0.y, v0.w, acc.w);
        acc.x = fmaf(e1.y, v1.x, acc.x); acc.y = fmaf(e1.y, v1.y, acc.y);
        acc.z = fmaf(e1.y, v1.z, acc.z); acc.w = fmaf(e1.y, v1.w, acc.w);
    }
    if (i < o1) {
        float2 e0 = g_csr[i];
        float4 v0 = x4[(long)__float_as_int(e0.x) * 2 + t];
        acc.x = fmaf(e0.y, v0.x, acc.x); acc.y = fmaf(e0.y, v0.y, acc.y);
        acc.z = fmaf(e0.y, v0.z, acc.z); acc.w = fmaf(e0.y, v0.w, acc.w);
    }
    ((float4*)g_aggx)[(long)n * 2 + t] = acc;
}

// ---------------- gather64: g_agg = A_hat @ g_xw (warp per node) ----------
// 32 lanes, each owns a float2 (8B) slice of the 256B row. CSR entries are
// warp-uniform broadcast loads; unroll 4 for MLP.
__global__ void k_gather64() {
    int gwid = (blockIdx.x * blockDim.x + threadIdx.x) >> 5;
    int lane = threadIdx.x & 31;
    if (gwid >= N_NODES) return;
    const float2* __restrict__ xw2 = (const float2*)g_xw;
    int o0 = g_off[gwid], o1 = g_off[gwid + 1];
    float dv = g_dinv[gwid];
    float2 acc = xw2[(long)gwid * 32 + lane];
    float d2 = dv * dv;
    acc.x *= d2; acc.y *= d2;
    int i = o0;
    for (; i + 4 <= o1; i += 4) {
        float2 e0 = g_csr[i], e1 = g_csr[i + 1], e2 = g_csr[i + 2], e3 = g_csr[i + 3];
        float2 v0 = xw2[(long)__float_as_int(e0.x) * 32 + lane];
        float2 v1 = xw2[(long)__float_as_int(e1.x) * 32 + lane];
        float2 v2 = xw2[(long)__float_as_int(e2.x) * 32 + lane];
        float2 v3 = xw2[(long)__float_as_int(e3.x) * 32 + lane];
        acc.x = fmaf(e0.y, v0.x, acc.x); acc.y = fmaf(e0.y, v0.y, acc.y);
        acc.x = fmaf(e1.y, v1.x, acc.x); acc.y = fmaf(e1.y, v1.y, acc.y);
        acc.x = fmaf(e2.y, v2.x, acc.x); acc.y = fmaf(e2.y, v2.y, acc.y);
        acc.x = fmaf(e3.y, v3.x, acc.x); acc.y = fmaf(e3.y, v3.y, acc.y);
    }
    for (; i < o1; i++) {
        float2 e0 = g_csr[i];
        float2 v0 = xw2[(long)__float_as_int(e0.x) * 32 + lane];
        acc.x = fmaf(e0.y, v0.x, acc.x); acc.y = fmaf(e0.y, v0.y, acc.y);
    }
    ((float2*)g_agg)[(long)gwid * 32 + lane] = acc;
}

// ---------------- GEMM K=8 (layer 1): g_xw = g_aggx @ W1 ------------------
__global__ void k_gemm8(const float* __restrict__ W) {
    constexpr int K = 8, WS = 12;
    __shared__ __align__(16) float Wt[64 * WS];
    __shared__ __align__(16) float S[16 * K];
    const int tid  = threadIdx.x;
    const int base = blockIdx.x * 16;
    for (int t = tid; t < 64 * K; t += 256) {
        int j = t & 63, k = t >> 6;
        Wt[j * WS + k] = W[k * 64 + j];
    }
    for (int t = tid; t < 16 * K; t += 256) {
        int r = t / K, k = t - r * K;
        S[r * K + k] = g_aggx[(long)(base + r) * K + k];
    }
    __syncthreads();
    const int r  = tid >> 4;
    const int jg = tid & 15;
    float acc[4] = {0.f, 0.f, 0.f, 0.f};
#pragma unroll
    for (int k4 = 0; k4 < K / 4; k4++) {
        float4 a = *(const float4*)&S[r * K + k4 * 4];
#pragma unroll
        for (int m = 0; m < 4; m++) {
            float4 w = *(const float4*)&Wt[(jg + 16 * m) * WS + k4 * 4];
            acc[m] += a.x * w.x + a.y * w.y + a.z * w.z + a.w * w.w;
        }
    }
    const int node = base + r;
#pragma unroll
    for (int m = 0; m < 4; m++)
        g_xw[(long)node * 64 + jg + 16 * m] = acc[m];
}

// ---------------- GEMM K=64, register-tiled 4x4: g_xw = relu(src+b) @ W ---
// SRC: 1 = g_xw (in-place, block-local rows), 2 = g_agg
// Block: 256 threads, 64 rows x 64 cols; thread = 4 rows x 4 cols.
template <int SRC>
__global__ void k_gemmT(const float* __restrict__ W, const float* __restrict__ bias) {
    __shared__ __align__(16) float S[64 * 68];   // padded rows
    __shared__ __align__(16) float Wm[64 * 64];  // natural [k][j]
    const float* s = (SRC == 1) ? g_xw : g_agg;
    const int tid  = threadIdx.x;
    const int base = blockIdx.x * 64;

    for (int i = tid; i < 1024; i += 256)
        ((float4*)Wm)[i] = ((const float4*)W)[i];
    for (int i = tid; i < 4096; i += 256) {
        int r = i >> 6, k = i & 63;
        int row = base + r;
        float v = (row < N_NODES) ? s[(long)row * 64 + k] : 0.0f;
        S[r * 68 + k] = fmaxf(v + bias[k], 0.0f);
    }
    __syncthreads();

    const int tx = tid & 15;        // col group: j = tx*4..tx*4+3
    const int ty = tid >> 4;        // row group: r = ty*4..ty*4+3
    float4 acc0 = {0,0,0,0}, acc1 = {0,0,0,0}, acc2 = {0,0,0,0}, acc3 = {0,0,0,0};
    const float* Sr = &S[ty * 4 * 68];
    const int jc = tx << 2;

#pragma unroll 4
    for (int k = 0; k < 64; k++) {
        float4 w = *(const float4*)&Wm[(k << 6) + jc];
        float s0 = Sr[k];
        float s1 = Sr[68 + k];
        float s2 = Sr[136 + k];
        float s3 = Sr[204 + k];
        acc0.x = fmaf(s0, w.x, acc0.x); acc0.y = fmaf(s0, w.y, acc0.y);
        acc0.z = fmaf(s0, w.z, acc0.z); acc0.w = fmaf(s0, w.w, acc0.w);
        acc1.x = fmaf(s1, w.x, acc1.x); acc1.y = fmaf(s1, w.y, acc1.y);
        acc1.z = fmaf(s1, w.z, acc1.z); acc1.w = fmaf(s1, w.w, acc1.w);
        acc2.x = fmaf(s2, w.x, acc2.x); acc2.y = fmaf(s2, w.y, acc2.y);
        acc2.z = fmaf(s2, w.z, acc2.z); acc2.w = fmaf(s2, w.w, acc2.w);
        acc3.x = fmaf(s3, w.x, acc3.x); acc3.y = fmaf(s3, w.y, acc3.y);
        acc3.z = fmaf(s3, w.z, acc3.z); acc3.w = fmaf(s3, w.w, acc3.w);
    }

    const int r0 = base + ty * 4;
    if (r0 + 0 < N_NODES) *(float4*)&g_xw[(long)(r0 + 0) * 64 + jc] = acc0;
    if (r0 + 1 < N_NODES) *(float4*)&g_xw[(long)(r0 + 1) * 64 + jc] = acc1;
    if (r0 + 2 < N_NODES) *(float4*)&g_xw[(long)(r0 + 2) * 64 + jc] = acc2;
    if (r0 + 3 < N_NODES) *(float4*)&g_xw[(long)(r0 + 3) * 64 + jc] = acc3;
}

// ---------------- pooling (sorted batch, run-length flush) ----------------
__global__ void k_pool(const float* __restrict__ b4, const int* __restrict__ batch) {
    int j = threadIdx.x & 63;
    int y = threadIdx.x >> 6;
    int start = blockIdx.x * 512 + y * 128;
    int end   = min(start + 128, N_NODES);
    if (start >= end) return;

    float bj = b4[j];
    int   curg = batch[start];
    float mx = 0.f, sm = 0.f;
    int   cnt = 0;

    for (int n = start; n < end; n++) {
        int g = batch[n];
        if (g != curg) {
            atomicMax((int*)&g_gmax[curg * 64 + j], __float_as_int(mx));
            atomicAdd(&g_gsum[curg * 64 + j], sm);
            if (j == 0) atomicAdd(&g_gcnt[curg], (float)cnt);
            curg = g; mx = 0.f; sm = 0.f; cnt = 0;
        }
        float v = fmaxf(g_agg[(long)n * 64 + j] + bj, 0.0f);
        mx = fmaxf(mx, v);
        sm += v;
        cnt++;
    }
    atomicMax((int*)&g_gmax[curg * 64 + j], __float_as_int(mx));
    atomicAdd(&g_gsum[curg * 64 + j], sm);
    if (j == 0) atomicAdd(&g_gcnt[curg], (float)cnt);
}

// ---------------- head ----------------------------------------------------
__global__ void k_head(const float* __restrict__ Wo, const float* __restrict__ bo,
                       float* __restrict__ out, int write_hg) {
    int g = blockIdx.x;
    int j = threadIdx.x;  // 0..127
    float cnt = fmaxf(g_gcnt[g], 1.0f);
    float val = (j < 64) ? g_gmax[g * 64 + j] : g_gsum[g * 64 + (j - 64)] / cnt;
    if (write_hg) out[N_GRAPHS + (long)g * 128 + j] = val;

    float p = val * Wo[j];
#pragma unroll
    for (int off = 16; off > 0; off >>= 1)
        p += __shfl_down_sync(0xffffffff, p, off);

    __shared__ float red[4];
    if ((j & 31) == 0) red[j >> 5] = p;
    __syncthreads();
    if (j == 0) out[g] = red[0] + red[1] + red[2] + red[3] + bo[0];
}

// ---------------- launch ---------------------------------------------------
extern "C" void kernel_launch(void* const* d_in, const int* in_sizes, int n_in,
                              void* d_out, int out_size) {
    const float* x     = (const float*)d_in[0];
    const int*   ei    = (const int*)  d_in[1];   // [2, E]
    const int*   batch = (const int*)  d_in[2];
    const float* W1 = (const float*)d_in[3];  const float* b1 = (const float*)d_in[4];
    const float* W2 = (const float*)d_in[5];  const float* b2 = (const float*)d_in[6];
    const float* W3 = (const float*)d_in[7];  const float* b3 = (const float*)d_in[8];
    const float* W4 = (const float*)d_in[9];  const float* b4 = (const float*)d_in[10];
    const float* Wo = (const float*)d_in[11]; const float* bo = (const float*)d_in[12];

    const int* rows = ei;            // source
    const int* cols = ei + N_EDGES;  // target

    float* out = (float*)d_out;
    int write_hg = (out_size >= N_GRAPHS + N_GRAPHS * 2 * HDIM) ? 1 : 0;

    const int NB_N = (N_NODES + 255) / 256;
    const int NB_E = (N_EDGES + 255) / 256;

    // CSR build
    k_zero     <<<NB_N, 256>>>();
    k_deg_count<<<NB_E, 256>>>(cols);
    k_scan1    <<<SCAN_NB, SCAN_B>>>();
    k_scan2    <<<1, 32>>>();
    k_scan3    <<<NB_N, 256>>>();
    k_fill     <<<NB_E, 256>>>(rows, cols);

    const int GX_BLKS   = (N_NODES * 2 + 255) / 256;
    const int G8_BLKS   = N_NODES / 16;                  // 6250 (exact)
    const int GT_BLKS   = (N_NODES + 63) / 64;           // 1563
    const int G64_BLKS  = (N_NODES * 32 + 255) / 256;    // 12500

    // layer 1: aggregate 8-dim input first, then GEMM
    k_gather_x<<<GX_BLKS, 256>>>(x);
    k_gemm8<<<G8_BLKS, 256>>>(W1);                 // g_xw = preact1
    // layer 2: xw2 = relu(preact1+b1) @ W2 (in-place), then aggregate
    k_gemmT<1><<<GT_BLKS, 256>>>(W2, b1);
    k_gather64<<<G64_BLKS, 256>>>();               // g_agg = preact2
    // layer 3
    k_gemmT<2><<<GT_BLKS, 256>>>(W3, b2);
    k_gather64<<<G64_BLKS, 256>>>();               // preact3
    // layer 4
    k_gemmT<2><<<GT_BLKS, 256>>>(W4, b3);
    k_gather64<<<G64_BLKS, 256>>>();               // preact4

    // pooling + head (relu(+b4) fused in pool)
    k_pool<<<(N_NODES + 511) / 512, 256>>>(b4, batch);
    k_head<<<N_GRAPHS, 128>>>(Wo, bo, out, write_hg);
}

// round 6
// speedup vs baseline: 1.8110x; 1.0974x over previous
#include <cuda_runtime.h>
#include <cuda_fp16.h>
#include <cuda_bf16.h>

#define N_NODES 100000
#define N_EDGES 1000000
#define N_GRAPHS 512
#define HDIM 64
#define SCAN_B 1024
#define SCAN_NB ((N_NODES + SCAN_B - 1) / SCAN_B)   // 98

// ---------------- scratch (device globals; never passed from host) --------
__device__ __align__(16) float  g_dinv[N_NODES];
__device__ __align__(16) int    g_deg [N_NODES];
__device__ __align__(16) int    g_off [N_NODES + 1];
__device__ __align__(16) int    g_cur [N_NODES];
__device__ __align__(16) int    g_bsum[SCAN_NB];
__device__ __align__(16) int    g_bpre[SCAN_NB];
__device__ __align__(16) float2 g_csr [N_EDGES];          // (src_as_int, norm)
__device__ __align__(16) __half g_xwh [N_NODES * HDIM];   // fp16 xw (gather operand)
__device__ __align__(16) float  g_agg [N_NODES * HDIM];   // fp32 preact
__device__ __align__(16) float  g_aggx[N_NODES * 8];
__device__ __align__(16) float  g_gmax[N_GRAPHS * HDIM];
__device__ __align__(16) float  g_gsum[N_GRAPHS * HDIM];
__device__ float g_gcnt[N_GRAPHS];

// ---------------- init: zero deg + pooling buffers ------------------------
__global__ void k_zero() {
    int i = blockIdx.x * blockDim.x + threadIdx.x;
    if (i < N_NODES) g_deg[i] = 0;
    if (i < N_GRAPHS * HDIM) { g_gmax[i] = 0.0f; g_gsum[i] = 0.0f; }
    if (i < N_GRAPHS) g_gcnt[i] = 0.0f;
}

__global__ void k_deg_count(const int* __restrict__ col) {
    int e = blockIdx.x * blockDim.x + threadIdx.x;
    if (e < N_EDGES) atomicAdd(&g_deg[col[e]], 1);
}

// ---------------- exclusive scan of g_deg -> g_off (+ dinv fused) ---------
__global__ void k_scan1() {   // grid SCAN_NB, block 1024
    __shared__ int sh[SCAN_B];
    int idx = threadIdx.x;
    int n = blockIdx.x * SCAN_B + idx;
    int v = (n < N_NODES) ? g_deg[n] : 0;
    if (n < N_NODES) g_dinv[n] = rsqrtf((float)(v + 1));  // +1 self-loop
    sh[idx] = v;
    __syncthreads();
#pragma unroll
    for (int d = 1; d < SCAN_B; d <<= 1) {
        int t = (idx >= d) ? sh[idx - d] : 0;
        __syncthreads();
        sh[idx] += t;
        __syncthreads();
    }
    if (n < N_NODES) g_off[n] = sh[idx] - v;          // exclusive (local)
    if (idx == SCAN_B - 1) g_bsum[blockIdx.x] = sh[idx];
}

__global__ void k_scan2() {   // 1 block, 128 threads: scan of 98 block sums
    __shared__ int sh[128];
    int t = threadIdx.x;
    int v = (t < SCAN_NB) ? g_bsum[t] : 0;
    sh[t] = v;
    __syncthreads();
#pragma unroll
    for (int d = 1; d < 128; d <<= 1) {
        int u = (t >= d) ? sh[t - d] : 0;
        __syncthreads();
        sh[t] += u;
        __syncthreads();
    }
    if (t < SCAN_NB) g_bpre[t] = sh[t] - v;           // exclusive
}

__global__ void k_scan3() {
    int n = blockIdx.x * blockDim.x + threadIdx.x;
    if (n < N_NODES) {
        int o = g_off[n] + g_bpre[n >> 10];
        g_off[n] = o;
        g_cur[n] = o;
    }
    if (n == 0) g_off[N_NODES] = N_EDGES;
}

// ---------------- CSR fill: packed (src, dinv[r]*dinv[c]) -----------------
__global__ void k_fill(const int* __restrict__ rows, const int* __restrict__ cols) {
    int e = blockIdx.x * blockDim.x + threadIdx.x;
    if (e >= N_EDGES) return;
    int r = rows[e], c = cols[e];
    int slot = atomicAdd(&g_cur[c], 1);
    g_csr[slot] = make_float2(__int_as_float(r), g_dinv[r] * g_dinv[c]);
}

// ---------------- gather_x: g_aggx = A_hat @ x (8-dim, fp32) --------------
__global__ void k_gather_x(const float* __restrict__ x) {
    int gid = blockIdx.x * blockDim.x + threadIdx.x;
    int n = gid >> 1, t = gid & 1;
    if (n >= N_NODES) return;
    const float4* x4 = (const float4*)x;
    int o0 = g_off[n], o1 = g_off[n + 1];
    float dv = g_dinv[n];
    float4 acc = x4[(long)n * 2 + t];
    float d2 = dv * dv;
    acc.x *= d2; acc.y *= d2; acc.z *= d2; acc.w *= d2;
    int i = o0;
    for (; i + 2 <= o1; i += 2) {
        float2 e0 = g_csr[i], e1 = g_csr[i + 1];
        float4 v0 = x4[(long)__float_as_int(e0.x) * 2 + t];
        float4 v1 = x4[(long)__float_as_int(e1.x) * 2 + t];
        acc.x = fmaf(e0.y, v0.x, acc.x); acc.y = fmaf(e0.y, v0.y, acc.y);
        acc.z = fmaf(e0.y, v0.z, acc.z); acc.w = fmaf(e0.y, v0.w, acc.w);
        acc.x = fmaf(e1.y, v1.x, acc.x); acc.y = fmaf(e1.y, v1.y, acc.y);
        acc.z = fmaf(e1.y, v1.z, acc.z); acc.w = fmaf(e1.y, v1.w, acc.w);
    }
    if (i < o1) {
        float2 e0 = g_csr[i];
        float4 v0 = x4[(long)__float_as_int(e0.x) * 2 + t];
        acc.x = fmaf(e0.y, v0.x, acc.x); acc.y = fmaf(e0.y, v0.y, acc.y);
        acc.z = fmaf(e0.y, v0.z, acc.z); acc.w = fmaf(e0.y, v0.w, acc.w);
    }
    ((float4*)g_aggx)[(long)n * 2 + t] = acc;
}

// ---------------- gather64: g_agg = A_hat @ xw (fp16 rows, warp/node) -----
// 32 lanes, each owns one half2 (4B) slice of the 128B fp16 row. The node's
// own self-loop term comes from g_xwh too (same quantization as neighbors).
__global__ void k_gather64() {
    int gwid = (blockIdx.x * blockDim.x + threadIdx.x) >> 5;
    int lane = threadIdx.x & 31;
    if (gwid >= N_NODES) return;
    const __half2* __restrict__ xw2 = (const __half2*)g_xwh;
    int o0 = g_off[gwid], o1 = g_off[gwid + 1];
    float dv = g_dinv[gwid];
    float2 self = __half22float2(xw2[(long)gwid * 32 + lane]);
    float d2 = dv * dv;
    float2 acc = make_float2(self.x * d2, self.y * d2);
    int i = o0;
    for (; i + 4 <= o1; i += 4) {
        float2 e0 = g_csr[i], e1 = g_csr[i + 1], e2 = g_csr[i + 2], e3 = g_csr[i + 3];
        float2 v0 = __half22float2(xw2[(long)__float_as_int(e0.x) * 32 + lane]);
        float2 v1 = __half22float2(xw2[(long)__float_as_int(e1.x) * 32 + lane]);
        float2 v2 = __half22float2(xw2[(long)__float_as_int(e2.x) * 32 + lane]);
        float2 v3 = __half22float2(xw2[(long)__float_as_int(e3.x) * 32 + lane]);
        acc.x = fmaf(e0.y, v0.x, acc.x); acc.y = fmaf(e0.y, v0.y, acc.y);
        acc.x = fmaf(e1.y, v1.x, acc.x); acc.y = fmaf(e1.y, v1.y, acc.y);
        acc.x = fmaf(e2.y, v2.x, acc.x); acc.y = fmaf(e2.y, v2.y, acc.y);
        acc.x = fmaf(e3.y, v3.x, acc.x); acc.y = fmaf(e3.y, v3.y, acc.y);
    }
    for (; i < o1; i++) {
        float2 e0 = g_csr[i];
        float2 v0 = __half22float2(xw2[(long)__float_as_int(e0.x) * 32 + lane]);
        acc.x = fmaf(e0.y, v0.x, acc.x); acc.y = fmaf(e0.y, v0.y, acc.y);
    }
    ((float2*)g_agg)[(long)gwid * 32 + lane] = acc;
}

// ---------------- GEMM K=8 (layer 1): g_agg = g_aggx @ W1 (fp32) ----------
__global__ void k_gemm8(const float* __restrict__ W) {
    constexpr int K = 8, WS = 12;
    __shared__ __align__(16) float Wt[64 * WS];
    __shared__ __align__(16) float S[16 * K];
    const int tid  = threadIdx.x;
    const int base = blockIdx.x * 16;
    for (int t = tid; t < 64 * K; t += 256) {
        int j = t & 63, k = t >> 6;
        Wt[j * WS + k] = W[k * 64 + j];
    }
    for (int t = tid; t < 16 * K; t += 256) {
        int r = t / K, k = t - r * K;
        S[r * K + k] = g_aggx[(long)(base + r) * K + k];
    }
    __syncthreads();
    const int r  = tid >> 4;
    const int jg = tid & 15;
    float acc[4] = {0.f, 0.f, 0.f, 0.f};
#pragma unroll
    for (int k4 = 0; k4 < K / 4; k4++) {
        float4 a = *(const float4*)&S[r * K + k4 * 4];
#pragma unroll
        for (int m = 0; m < 4; m++) {
            float4 w = *(const float4*)&Wt[(jg + 16 * m) * WS + k4 * 4];
            acc[m] += a.x * w.x + a.y * w.y + a.z * w.z + a.w * w.w;
        }
    }
    const int node = base + r;
#pragma unroll
    for (int m = 0; m < 4; m++)
        g_agg[(long)node * 64 + jg + 16 * m] = acc[m];
}

// ---------------- GEMM K=64, reg-tiled 4x4: g_xwh = relu(g_agg+b) @ W -----
// Block: 256 threads, 64 rows x 64 cols; thread = 4 rows x 4 cols.
__global__ void k_gemmT(const float* __restrict__ W, const float* __restrict__ bias) {
    __shared__ __align__(16) float S[64 * 68];   // padded rows
    __shared__ __align__(16) float Wm[64 * 64];  // natural [k][j]
    const int tid  = threadIdx.x;
    const int base = blockIdx.x * 64;

    for (int i = tid; i < 1024; i += 256)
        ((float4*)Wm)[i] = ((const float4*)W)[i];
    for (int i = tid; i < 4096; i += 256) {
        int r = i >> 6, k = i & 63;
        int row = base + r;
        float v = (row < N_NODES) ? g_agg[(long)row * 64 + k] : 0.0f;
        S[r * 68 + k] = fmaxf(v + bias[k], 0.0f);
    }
    __syncthreads();

    const int tx = tid & 15;        // col group: j = tx*4..tx*4+3
    const int ty = tid >> 4;        // row group: r = ty*4..ty*4+3
    float4 acc0 = {0,0,0,0}, acc1 = {0,0,0,0}, acc2 = {0,0,0,0}, acc3 = {0,0,0,0};
    const float* Sr = &S[ty * 4 * 68];
    const int jc = tx << 2;

#pragma unroll 4
    for (int k = 0; k < 64; k++) {
        float4 w = *(const float4*)&Wm[(k << 6) + jc];
        float s0 = Sr[k];
        float s1 = Sr[68 + k];
        float s2 = Sr[136 + k];
        float s3 = Sr[204 + k];
        acc0.x = fmaf(s0, w.x, acc0.x); acc0.y = fmaf(s0, w.y, acc0.y);
        acc0.z = fmaf(s0, w.z, acc0.z); acc0.w = fmaf(s0, w.w, acc0.w);
        acc1.x = fmaf(s1, w.x, acc1.x); acc1.y = fmaf(s1, w.y, acc1.y);
        acc1.z = fmaf(s1, w.z, acc1.z); acc1.w = fmaf(s1, w.w, acc1.w);
        acc2.x = fmaf(s2, w.x, acc2.x); acc2.y = fmaf(s2, w.y, acc2.y);
        acc2.z = fmaf(s2, w.z, acc2.z); acc2.w = fmaf(s2, w.w, acc2.w);
        acc3.x = fmaf(s3, w.x, acc3.x); acc3.y = fmaf(s3, w.y, acc3.y);
        acc3.z = fmaf(s3, w.z, acc3.z); acc3.w = fmaf(s3, w.w, acc3.w);
    }

    const int r0 = base + ty * 4;
#pragma unroll
    for (int m = 0; m < 4; m++) {
        float4 a = (m == 0) ? acc0 : (m == 1) ? acc1 : (m == 2) ? acc2 : acc3;
        int row = r0 + m;
        if (row < N_NODES) {
            __half2 pair[2];
            pair[0] = __floats2half2_rn(a.x, a.y);
            pair[1] = __floats2half2_rn(a.z, a.w);
            *(uint2*)&g_xwh[(long)row * 64 + jc] = *(uint2*)pair;  // 8B store
        }
    }
}

// ---------------- pooling (sorted batch, run-length flush) ----------------
__global__ void k_pool(const float* __restrict__ b4, const int* __restrict__ batch) {
    int j = threadIdx.x & 63;
    int y = threadIdx.x >> 6;
    int start = blockIdx.x * 512 + y * 128;
    int end   = min(start + 128, N_NODES);
    if (start >= end) return;

    float bj = b4[j];
    int   curg = batch[start];
    float mx = 0.f, sm = 0.f;
    int   cnt = 0;

    for (int n = start; n < end; n++) {
        int g = batch[n];
        if (g != curg) {
            atomicMax((int*)&g_gmax[curg * 64 + j], __float_as_int(mx));
            atomicAdd(&g_gsum[curg * 64 + j], sm);
            if (j == 0) atomicAdd(&g_gcnt[curg], (float)cnt);
            curg = g; mx = 0.f; sm = 0.f; cnt = 0;
        }
        float v = fmaxf(g_agg[(long)n * 64 + j] + bj, 0.0f);
        mx = fmaxf(mx, v);
        sm += v;
        cnt++;
    }
    atomicMax((int*)&g_gmax[curg * 64 + j], __float_as_int(mx));
    atomicAdd(&g_gsum[curg * 64 + j], sm);
    if (j == 0) atomicAdd(&g_gcnt[curg], (float)cnt);
}

// ---------------- head ----------------------------------------------------
__global__ void k_head(const float* __restrict__ Wo, const float* __restrict__ bo,
                       float* __restrict__ out, int write_hg) {
    int g = blockIdx.x;
    int j = threadIdx.x;  // 0..127
    float cnt = fmaxf(g_gcnt[g], 1.0f);
    float val = (j < 64) ? g_gmax[g * 64 + j] : g_gsum[g * 64 + (j - 64)] / cnt;
    if (write_hg) out[N_GRAPHS + (long)g * 128 + j] = val;

    float p = val * Wo[j];
#pragma unroll
    for (int off = 16; off > 0; off >>= 1)
        p += __shfl_down_sync(0xffffffff, p, off);

    __shared__ float red[4];
    if ((j & 31) == 0) red[j >> 5] = p;
    __syncthreads();
    if (j == 0) out[g] = red[0] + red[1] + red[2] + red[3] + bo[0];
}

// ---------------- launch ---------------------------------------------------
extern "C" void kernel_launch(void* const* d_in, const int* in_sizes, int n_in,
                              void* d_out, int out_size) {
    const float* x     = (const float*)d_in[0];
    const int*   ei    = (const int*)  d_in[1];   // [2, E]
    const int*   batch = (const int*)  d_in[2];
    const float* W1 = (const float*)d_in[3];  const float* b1 = (const float*)d_in[4];
    const float* W2 = (const float*)d_in[5];  const float* b2 = (const float*)d_in[6];
    const float* W3 = (const float*)d_in[7];  const float* b3 = (const float*)d_in[8];
    const float* W4 = (const float*)d_in[9];  const float* b4 = (const float*)d_in[10];
    const float* Wo = (const float*)d_in[11]; const float* bo = (const float*)d_in[12];

    const int* rows = ei;            // source
    const int* cols = ei + N_EDGES;  // target

    float* out = (float*)d_out;
    int write_hg = (out_size >= N_GRAPHS + N_GRAPHS * 2 * HDIM) ? 1 : 0;

    const int NB_N = (N_NODES + 255) / 256;
    const int NB_E = (N_EDGES + 255) / 256;

    // CSR build
    k_zero     <<<NB_N, 256>>>();
    k_deg_count<<<NB_E, 256>>>(cols);
    k_scan1    <<<SCAN_NB, SCAN_B>>>();
    k_scan2    <<<1, 128>>>();
    k_scan3    <<<NB_N, 256>>>();
    k_fill     <<<NB_E, 256>>>(rows, cols);

    const int GX_BLKS   = (N_NODES * 2 + 255) / 256;
    const int G8_BLKS   = N_NODES / 16;                  // 6250 (exact)
    const int GT_BLKS   = (N_NODES + 63) / 64;           // 1563
    const int G64_BLKS  = (N_NODES * 32 + 255) / 256;    // 12500

    // layer 1: aggregate 8-dim input first, then GEMM -> g_agg (preact1, fp32)
    k_gather_x<<<GX_BLKS, 256>>>(x);
    k_gemm8<<<G8_BLKS, 256>>>(W1);
    // layers 2..4: g_xwh = relu(g_agg + b_prev) @ W (fp16), then aggregate
    k_gemmT<<<GT_BLKS, 256>>>(W2, b1);
    k_gather64<<<G64_BLKS, 256>>>();               // g_agg = preact2
    k_gemmT<<<GT_BLKS, 256>>>(W3, b2);
    k_gather64<<<G64_BLKS, 256>>>();               // preact3
    k_gemmT<<<GT_BLKS, 256>>>(W4, b3);
    k_gather64<<<G64_BLKS, 256>>>();               // preact4

    // pooling + head (relu(+b4) fused in pool)
    k_pool<<<(N_NODES + 511) / 512, 256>>>(b4, batch);
    k_head<<<N_GRAPHS, 128>>>(Wo, bo, out, write_hg);
}

// round 7
// speedup vs baseline: 1.8209x; 1.0055x over previous
#include <cuda_runtime.h>
#include <cuda_fp16.h>
#include <cuda_bf16.h>

#define N_NODES 100000
#define N_EDGES 1000000
#define N_GRAPHS 512
#define HDIM 64
#define SCAN_B 1024
#define SCAN_NB ((N_NODES + SCAN_B - 1) / SCAN_B)   // 98

// ---------------- scratch (device globals; never passed from host) --------
// g_deg is self-cleaning: k_scan1 zeroes it after reading, so every call
// starts from zero (globals are zero-initialized at load).
__device__ __align__(16) float  g_dinv[N_NODES];
__device__ __align__(16) int    g_deg [N_NODES];
__device__ __align__(16) int    g_off [N_NODES + 1];
__device__ __align__(16) int    g_cur [N_NODES];
__device__ __align__(16) int    g_bsum[SCAN_NB];
__device__ __align__(16) float2 g_csr [N_EDGES];          // (src_as_int, norm)
__device__ __align__(16) __half g_xwh [N_NODES * HDIM];   // fp16 xw (gather operand)
__device__ __align__(16) float  g_agg [N_NODES * HDIM];   // fp32 preact
__device__ __align__(16) float  g_gmax[N_GRAPHS * HDIM];
__device__ __align__(16) float  g_gsum[N_GRAPHS * HDIM];
__device__ float g_gcnt[N_GRAPHS];

// ---------------- degree count (4 edges/thread) ---------------------------
__global__ void k_deg_count(const int* __restrict__ col) {
    int q = blockIdx.x * blockDim.x + threadIdx.x;
    if (q >= N_EDGES / 4) return;
    int4 c4 = ((const int4*)col)[q];
    atomicAdd(&g_deg[c4.x], 1);
    atomicAdd(&g_deg[c4.y], 1);
    atomicAdd(&g_deg[c4.z], 1);
    atomicAdd(&g_deg[c4.w], 1);
}

// ---------------- scan stage 1: per-chunk scan + dinv + deg self-zero -----
__global__ void k_scan1() {   // grid SCAN_NB, block 1024
    __shared__ int sh[SCAN_B];
    int idx = threadIdx.x;
    int n = blockIdx.x * SCAN_B + idx;
    int v = 0;
    if (n < N_NODES) {
        v = g_deg[n];
        g_deg[n] = 0;                          // clean for next call
        g_dinv[n] = rsqrtf((float)(v + 1));    // +1 self-loop
    }
    sh[idx] = v;
    __syncthreads();
#pragma unroll
    for (int d = 1; d < SCAN_B; d <<= 1) {
        int t = (idx >= d) ? sh[idx - d] : 0;
        __syncthreads();
        sh[idx] += t;
        __syncthreads();
    }
    if (n < N_NODES) g_off[n] = sh[idx] - v;          // exclusive (local)
    if (idx == SCAN_B - 1) g_bsum[blockIdx.x] = sh[idx];
}

// ---------------- scan stage 2: apply chunk prefixes (redundant per-block
// scan of the 98 chunk sums) + init g_cur + zero pooling buffers ----------
__global__ void k_scan3() {   // grid ceil(N/256), block 256
    __shared__ int sh[128];
    int t = threadIdx.x;
    int v = 0;
    if (t < 128) {
        v = (t < SCAN_NB) ? g_bsum[t] : 0;
        sh[t] = v;
    }
    __syncthreads();
#pragma unroll
    for (int d = 1; d < 128; d <<= 1) {
        int u = 0;
        if (t < 128 && t >= d) u = sh[t - d];
        __syncthreads();
        if (t < 128) sh[t] += u;
        __syncthreads();
    }
    if (t < 128) sh[t] -= v;   // exclusive chunk prefix
    __syncthreads();

    int n = blockIdx.x * 256 + t;
    if (n < N_NODES) {
        int o = g_off[n] + sh[n >> 10];
        g_off[n] = o;
        g_cur[n] = o;
    }
    if (n == 0) g_off[N_NODES] = N_EDGES;
    // zero pooling buffers (consumed much later by k_pool)
    if (n < N_GRAPHS * HDIM) { g_gmax[n] = 0.0f; g_gsum[n] = 0.0f; }
    if (n < N_GRAPHS) g_gcnt[n] = 0.0f;
}

// ---------------- CSR fill: packed (src, dinv[r]*dinv[c]), 4 edges/thr ----
__global__ void k_fill(const int* __restrict__ rows, const int* __restrict__ cols) {
    int q = blockIdx.x * blockDim.x + threadIdx.x;
    if (q >= N_EDGES / 4) return;
    int4 r4 = ((const int4*)rows)[q];
    int4 c4 = ((const int4*)cols)[q];
#pragma unroll
    for (int m = 0; m < 4; m++) {
        int r = (m == 0) ? r4.x : (m == 1) ? r4.y : (m == 2) ? r4.z : r4.w;
        int c = (m == 0) ? c4.x : (m == 1) ? c4.y : (m == 2) ? c4.z : c4.w;
        int slot = atomicAdd(&g_cur[c], 1);
        g_csr[slot] = make_float2(__int_as_float(r), g_dinv[r] * g_dinv[c]);
    }
}

// ---------------- layer 1 fused: g_agg = (A_hat @ x) @ W1 -----------------
// Block 256 threads = 128 nodes. Phase 1: 2 thr/node gather 8-dim row into
// smem. Phase 2: 2 thr/node matvec (32 cols each) with smem W1.
__global__ void k_l1(const float* __restrict__ x, const float* __restrict__ W1) {
    __shared__ __align__(16) float W1s[8 * 64];
    __shared__ __align__(16) float A[128 * 8];
    const int tid  = threadIdx.x;
    const int nloc = tid >> 1;
    const int half = tid & 1;
    const int n    = blockIdx.x * 128 + nloc;

    // load W1 (2KB)
    for (int i = tid; i < 512; i += 256) W1s[i] = W1[i];

    if (n < N_NODES) {
        const float4* x4 = (const float4*)x;
        int o0 = g_off[n], o1 = g_off[n + 1];
        float dv = g_dinv[n];
        float4 acc = x4[(long)n * 2 + half];
        float d2 = dv * dv;
        acc.x *= d2; acc.y *= d2; acc.z *= d2; acc.w *= d2;
        int i = o0;
        for (; i + 2 <= o1; i += 2) {
            float2 e0 = g_csr[i], e1 = g_csr[i + 1];
            float4 v0 = x4[(long)__float_as_int(e0.x) * 2 + half];
            float4 v1 = x4[(long)__float_as_int(e1.x) * 2 + half];
            acc.x = fmaf(e0.y, v0.x, acc.x); acc.y = fmaf(e0.y, v0.y, acc.y);
            acc.z = fmaf(e0.y, v0.z, acc.z); acc.w = fmaf(e0.y, v0.w, acc.w);
            acc.x = fmaf(e1.y, v1.x, acc.x); acc.y = fmaf(e1.y, v1.y, acc.y);
            acc.z = fmaf(e1.y, v1.z, acc.z); acc.w = fmaf(e1.y, v1.w, acc.w);
        }
        if (i < o1) {
            float2 e0 = g_csr[i];
            float4 v0 = x4[(long)__float_as_int(e0.x) * 2 + half];
            acc.x = fmaf(e0.y, v0.x, acc.x); acc.y = fmaf(e0.y, v0.y, acc.y);
            acc.z = fmaf(e0.y, v0.z, acc.z); acc.w = fmaf(e0.y, v0.w, acc.w);
        }
        *(float4*)&A[nloc * 8 + half * 4] = acc;
    }
    __syncthreads();

    if (n < N_NODES) {
        float a[8];
        *(float4*)&a[0] = *(const float4*)&A[nloc * 8];
        *(float4*)&a[4] = *(const float4*)&A[nloc * 8 + 4];
        const int jc0 = half * 32;
        float4 acc[8];
#pragma unroll
        for (int g = 0; g < 8; g++) acc[g] = make_float4(0.f, 0.f, 0.f, 0.f);
#pragma unroll
        for (int k = 0; k < 8; k++) {
            float ak = a[k];
#pragma unroll
            for (int g = 0; g < 8; g++) {
                float4 w = *(const float4*)&W1s[k * 64 + jc0 + g * 4];
                acc[g].x = fmaf(ak, w.x, acc[g].x);
                acc[g].y = fmaf(ak, w.y, acc[g].y);
                acc[g].z = fmaf(ak, w.z, acc[g].z);
                acc[g].w = fmaf(ak, w.w, acc[g].w);
            }
        }
#pragma unroll
        for (int g = 0; g < 8; g++)
            *(float4*)&g_agg[(long)n * 64 + jc0 + g * 4] = acc[g];
    }
}

// ---------------- gather64: g_agg = A_hat @ xw (fp16 rows, warp/node) -----
__global__ void k_gather64() {
    int gwid = (blockIdx.x * blockDim.x + threadIdx.x) >> 5;
    int lane = threadIdx.x & 31;
    if (gwid >= N_NODES) return;
    const __half2* __restrict__ xw2 = (const __half2*)g_xwh;
    int o0 = g_off[gwid], o1 = g_off[gwid + 1];
    float dv = g_dinv[gwid];
    float2 self = __half22float2(xw2[(long)gwid * 32 + lane]);
    float d2 = dv * dv;
    float2 acc = make_float2(self.x * d2, self.y * d2);
    int i = o0;
    for (; i + 4 <= o1; i += 4) {
        float2 e0 = g_csr[i], e1 = g_csr[i + 1], e2 = g_csr[i + 2], e3 = g_csr[i + 3];
        float2 v0 = __half22float2(xw2[(long)__float_as_int(e0.x) * 32 + lane]);
        float2 v1 = __half22float2(xw2[(long)__float_as_int(e1.x) * 32 + lane]);
        float2 v2 = __half22float2(xw2[(long)__float_as_int(e2.x) * 32 + lane]);
        float2 v3 = __half22float2(xw2[(long)__float_as_int(e3.x) * 32 + lane]);
        acc.x = fmaf(e0.y, v0.x, acc.x); acc.y = fmaf(e0.y, v0.y, acc.y);
        acc.x = fmaf(e1.y, v1.x, acc.x); acc.y = fmaf(e1.y, v1.y, acc.y);
        acc.x = fmaf(e2.y, v2.x, acc.x); acc.y = fmaf(e2.y, v2.y, acc.y);
        acc.x = fmaf(e3.y, v3.x, acc.x); acc.y = fmaf(e3.y, v3.y, acc.y);
    }
    for (; i < o1; i++) {
        float2 e0 = g_csr[i];
        float2 v0 = __half22float2(xw2[(long)__float_as_int(e0.x) * 32 + lane]);
        acc.x = fmaf(e0.y, v0.x, acc.x); acc.y = fmaf(e0.y, v0.y, acc.y);
    }
    ((float2*)g_agg)[(long)gwid * 32 + lane] = acc;
}

// ---------------- GEMM K=64, reg-tiled 4x4: g_xwh = relu(g_agg+b) @ W -----
__global__ __launch_bounds__(256) void k_gemmT(const float* __restrict__ W,
                                               const float* __restrict__ bias) {
    __shared__ __align__(16) float S[64 * 68];   // padded rows
    __shared__ __align__(16) float Wm[64 * 64];  // natural [k][j]
    const int tid  = threadIdx.x;
    const int base = blockIdx.x * 64;

    for (int i = tid; i < 1024; i += 256)
        ((float4*)Wm)[i] = ((const float4*)W)[i];
    for (int i = tid; i < 4096; i += 256) {
        int r = i >> 6, k = i & 63;
        int row = base + r;
        float v = (row < N_NODES) ? g_agg[(long)row * 64 + k] : 0.0f;
        S[r * 68 + k] = fmaxf(v + bias[k], 0.0f);
    }
    __syncthreads();

    const int tx = tid & 15;        // col group: j = tx*4..tx*4+3
    const int ty = tid >> 4;        // row group: r = ty*4..ty*4+3
    float4 acc0 = {0,0,0,0}, acc1 = {0,0,0,0}, acc2 = {0,0,0,0}, acc3 = {0,0,0,0};
    const float* Sr = &S[ty * 4 * 68];
    const int jc = tx << 2;

#pragma unroll
    for (int k4 = 0; k4 < 16; k4++) {
        const int kb = k4 * 4;
        float4 a0 = *(const float4*)&Sr[kb];
        float4 a1 = *(const float4*)&Sr[68 + kb];
        float4 a2 = *(const float4*)&Sr[136 + kb];
        float4 a3 = *(const float4*)&Sr[204 + kb];
        float4 w0 = *(const float4*)&Wm[(kb + 0) * 64 + jc];
        float4 w1 = *(const float4*)&Wm[(kb + 1) * 64 + jc];
        float4 w2 = *(const float4*)&Wm[(kb + 2) * 64 + jc];
        float4 w3 = *(const float4*)&Wm[(kb + 3) * 64 + jc];

        acc0.x = fmaf(a0.x, w0.x, acc0.x); acc0.y = fmaf(a0.x, w0.y, acc0.y);
        acc0.z = fmaf(a0.x, w0.z, acc0.z); acc0.w = fmaf(a0.x, w0.w, acc0.w);
        acc0.x = fmaf(a0.y, w1.x, acc0.x); acc0.y = fmaf(a0.y, w1.y, acc0.y);
        acc0.z = fmaf(a0.y, w1.z, acc0.z); acc0.w = fmaf(a0.y, w1.w, acc0.w);
        acc0.x = fmaf(a0.z, w2.x, acc0.x); acc0.y = fmaf(a0.z, w2.y, acc0.y);
        acc0.z = fmaf(a0.z, w2.z, acc0.z); acc0.w = fmaf(a0.z, w2.w, acc0.w);
        acc0.x = fmaf(a0.w, w3.x, acc0.x); acc0.y = fmaf(a0.w, w3.y, acc0.y);
        acc0.z = fmaf(a0.w, w3.z, acc0.z); acc0.w = fmaf(a0.w, w3.w, acc0.w);

        acc1.x = fmaf(a1.x, w0.x, acc1.x); acc1.y = fmaf(a1.x, w0.y, acc1.y);
        acc1.z = fmaf(a1.x, w0.z, acc1.z); acc1.w = fmaf(a1.x, w0.w, acc1.w);
        acc1.x = fmaf(a1.y, w1.x, acc1.x); acc1.y = fmaf(a1.y, w1.y, acc1.y);
        acc1.z = fmaf(a1.y, w1.z, acc1.z); acc1.w = fmaf(a1.y, w1.w, acc1.w);
        acc1.x = fmaf(a1.z, w2.x, acc1.x); acc1.y = fmaf(a1.z, w2.y, acc1.y);
        acc1.z = fmaf(a1.z, w2.z, acc1.z); acc1.w = fmaf(a1.z, w2.w, acc1.w);
        acc1.x = fmaf(a1.w, w3.x, acc1.x); acc1.y = fmaf(a1.w, w3.y, acc1.y);
        acc1.z = fmaf(a1.w, w3.z, acc1.z); acc1.w = fmaf(a1.w, w3.w, acc1.w);

        acc2.x = fmaf(a2.x, w0.x, acc2.x); acc2.y = fmaf(a2.x, w0.y, acc2.y);
        acc2.z = fmaf(a2.x, w0.z, acc2.z); acc2.w = fmaf(a2.x, w0.w, acc2.w);
        acc2.x = fmaf(a2.y, w1.x, acc2.x); acc2.y = fmaf(a2.y, w1.y, acc2.y);
        acc2.z = fmaf(a2.y, w1.z, acc2.z); acc2.w = fmaf(a2.y, w1.w, acc2.w);
        acc2.x = fmaf(a2.z, w2.x, acc2.x); acc2.y = fmaf(a2.z, w2.y, acc2.y);
        acc2.z = fmaf(a2.z, w2.z, acc2.z); acc2.w = fmaf(a2.z, w2.w, acc2.w);
        acc2.x = fmaf(a2.w, w3.x, acc2.x); acc2.y = fmaf(a2.w, w3.y, acc2.y);
        acc2.z = fmaf(a2.w, w3.z, acc2.z); acc2.w = fmaf(a2.w, w3.w, acc2.w);

        acc3.x = fmaf(a3.x, w0.x, acc3.x); acc3.y = fmaf(a3.x, w0.y, acc3.y);
        acc3.z = fmaf(a3.x, w0.z, acc3.z); acc3.w = fmaf(a3.x, w0.w, acc3.w);
        acc3.x = fmaf(a3.y, w1.x, acc3.x); acc3.y = fmaf(a3.y, w1.y, acc3.y);
        acc3.z = fmaf(a3.y, w1.z, acc3.z); acc3.w = fmaf(a3.y, w1.w, acc3.w);
        acc3.x = fmaf(a3.z, w2.x, acc3.x); acc3.y = fmaf(a3.z, w2.y, acc3.y);
        acc3.z = fmaf(a3.z, w2.z, acc3.z); acc3.w = fmaf(a3.z, w2.w, acc3.w);
        acc3.x = fmaf(a3.w, w3.x, acc3.x); acc3.y = fmaf(a3.w, w3.y, acc3.y);
        acc3.z = fmaf(a3.w, w3.z, acc3.z); acc3.w = fmaf(a3.w, w3.w, acc3.w);
    }

    const int r0 = base + ty * 4;
#pragma unroll
    for (int m = 0; m < 4; m++) {
        float4 a = (m == 0) ? acc0 : (m == 1) ? acc1 : (m == 2) ? acc2 : acc3;
        int row = r0 + m;
        if (row < N_NODES) {
            __half2 pair[2];
            pair[0] = __floats2half2_rn(a.x, a.y);
            pair[1] = __floats2half2_rn(a.z, a.w);
            *(uint2*)&g_xwh[(long)row * 64 + jc] = *(uint2*)pair;  // 8B store
        }
    }
}

// ---------------- pooling (sorted batch, run-length flush) ----------------
__global__ void k_pool(const float* __restrict__ b4, const int* __restrict__ batch) {
    int j = threadIdx.x & 63;
    int y = threadIdx.x >> 6;
    int start = blockIdx.x * 512 + y * 128;
    int end   = min(start + 128, N_NODES);
    if (start >= end) return;

    float bj = b4[j];
    int   curg = batch[start];
    float mx = 0.f, sm = 0.f;
    int   cnt = 0;

    for (int n = start; n < end; n++) {
        int g = batch[n];
        if (g != curg) {
            atomicMax((int*)&g_gmax[curg * 64 + j], __float_as_int(mx));
            atomicAdd(&g_gsum[curg * 64 + j], sm);
            if (j == 0) atomicAdd(&g_gcnt[curg], (float)cnt);
            curg = g; mx = 0.f; sm = 0.f; cnt = 0;
        }
        float v = fmaxf(g_agg[(long)n * 64 + j] + bj, 0.0f);
        mx = fmaxf(mx, v);
        sm += v;
        cnt++;
    }
    atomicMax((int*)&g_gmax[curg * 64 + j], __float_as_int(mx));
    atomicAdd(&g_gsum[curg * 64 + j], sm);
    if (j == 0) atomicAdd(&g_gcnt[curg], (float)cnt);
}

// ---------------- head ----------------------------------------------------
__global__ void k_head(const float* __restrict__ Wo, const float* __restrict__ bo,
                       float* __restrict__ out, int write_hg) {
    int g = blockIdx.x;
    int j = threadIdx.x;  // 0..127
    float cnt = fmaxf(g_gcnt[g], 1.0f);
    float val = (j < 64) ? g_gmax[g * 64 + j] : g_gsum[g * 64 + (j - 64)] / cnt;
    if (write_hg) out[N_GRAPHS + (long)g * 128 + j] = val;

    float p = val * Wo[j];
#pragma unroll
    for (int off = 16; off > 0; off >>= 1)
        p += __shfl_down_sync(0xffffffff, p, off);

    __shared__ float red[4];
    if ((j & 31) == 0) red[j >> 5] = p;
    __syncthreads();
    if (j == 0) out[g] = red[0] + red[1] + red[2] + red[3] + bo[0];
}

// ---------------- launch ---------------------------------------------------
extern "C" void kernel_launch(void* const* d_in, const int* in_sizes, int n_in,
                              void* d_out, int out_size) {
    const float* x     = (const float*)d_in[0];
    const int*   ei    = (const int*)  d_in[1];   // [2, E]
    const int*   batch = (const int*)  d_in[2];
    const float* W1 = (const float*)d_in[3];  const float* b1 = (const float*)d_in[4];
    const float* W2 = (const float*)d_in[5];  const float* b2 = (const float*)d_in[6];
    const float* W3 = (const float*)d_in[7];  const float* b3 = (const float*)d_in[8];
    const float* W4 = (const float*)d_in[9];  const float* b4 = (const float*)d_in[10];
    const float* Wo = (const float*)d_in[11]; const float* bo = (const float*)d_in[12];

    const int* rows = ei;            // source
    const int* cols = ei + N_EDGES;  // target

    float* out = (float*)d_out;
    int write_hg = (out_size >= N_GRAPHS + N_GRAPHS * 2 * HDIM) ? 1 : 0;

    const int NB_N  = (N_NODES + 255) / 256;
    const int NB_E4 = (N_EDGES / 4 + 255) / 256;

    // CSR build (g_deg arrives zeroed from previous call / load-time init)
    k_deg_count<<<NB_E4, 256>>>(cols);
    k_scan1    <<<SCAN_NB, SCAN_B>>>();
    k_scan3    <<<NB_N, 256>>>();
    k_fill     <<<NB_E4, 256>>>(rows, cols);

    const int L1_BLKS  = (N_NODES + 127) / 128;          // 782
    const int GT_BLKS  = (N_NODES + 63) / 64;            // 1563
    const int G64_BLKS = (N_NODES * 32 + 255) / 256;     // 12500

    // layer 1: fused 8-dim gather + GEMM -> g_agg = preact1 (fp32)
    k_l1<<<L1_BLKS, 256>>>(x, W1);
    // layers 2..4: g_xwh = relu(g_agg + b_prev) @ W (fp16), then aggregate
    k_gemmT<<<GT_BLKS, 256>>>(W2, b1);
    k_gather64<<<G64_BLKS, 256>>>();               // g_agg = preact2
    k_gemmT<<<GT_BLKS, 256>>>(W3, b2);
    k_gather64<<<G64_BLKS, 256>>>();               // preact3
    k_gemmT<<<GT_BLKS, 256>>>(W4, b3);
    k_gather64<<<G64_BLKS, 256>>>();               // preact4

    // pooling + head (relu(+b4) fused in pool)
    k_pool<<<(N_NODES + 511) / 512, 256>>>(b4, batch);
    k_head<<<N_GRAPHS, 128>>>(Wo, bo, out, write_hg);
}